// round 10
// baseline (speedup 1.0000x reference)
#include <cuda_runtime.h>

// Shapes fixed by reference setup_inputs
#define B_DIM 128
#define N_DIM 1024
#define K_DIM 512            // D*S
#define K_VEC (K_DIM / 4)    // 128 float4 per row
#define ALPHA 0.05f
#define THETA_LR 0.1f
#define R_TARGET 0.1f

// Dynamic-dispatch variant. Three single-wave configs all plateaued at
// ~6.3 TB/s (DRAM 79-81%) with MLP 6x oversubscribed -> the limiter is the
// per-SM straggler tail of a statically-pinned single wave (B300 spr floor
// 1.10-1.17 from L2-die variance / L1tex-queue unfairness). Fix: 16384 small
// work units (grid 16384, block 64 = 2 warps; each warp = 4 batch rows of one
// neuron) -> ~16 CTAs/SM resident, ~7 sequential rounds; the HW queue feeds
// freed slots, so fast SMs take more units and the tail shrinks to ~1 unit.
//
// Rate finalization: 32 warps contribute to each neuron. Device-scope
// counters (zero-init __device__ globals) accumulate spike counts; the
// 32nd-arriving warp reads the total and RESETS both counters via atomicExch
// so every graph replay starts from the same state (deterministic).
// Per-row FMA order + butterfly identical to the best passing kernel ->
// spikes bit-identical; counts are exact integers -> order-independent.

__device__ int g_cnt[N_DIM];       // zero-initialized at module load
__device__ int g_arrivals[N_DIM];  // zero-initialized at module load

__global__ __launch_bounds__(64) void mpjrd_dyn(
    const float4* __restrict__ x,     // [B, N, 128] float4
    const float4* __restrict__ W,     // [N, 128] float4
    const float* __restrict__ theta,  // [N]
    const float* __restrict__ r_hat,  // [N]
    float* __restrict__ spikes,       // [B, N]
    float* __restrict__ rates,        // [N]
    float* __restrict__ thetas,       // [N]
    float* __restrict__ r_hats)       // [N]
{
    const int u     = blockIdx.x;            // 0..16383
    const int n     = u & (N_DIM - 1);       // neuron
    const int slice = u >> 10;               // 0..15 (8 rows each)
    const int w     = threadIdx.x >> 5;      // warp 0..1
    const int lane  = threadIdx.x & 31;
    const int bb    = slice * 8 + w * 4;     // this warp's 4 batch rows

    // W row into registers (L2-resident after first touch; 2 KB per warp)
    const float4* wr = W + (size_t)n * K_VEC;
    float4 wreg[4];
#pragma unroll
    for (int k = 0; k < 4; k++) wreg[k] = __ldg(&wr[lane + 32 * k]);

    const float th = __ldg(&theta[n]);

    int cnt = 0;

    // 4 rows, 2 at a time (8 LDG.128 in flight), identical math order to R4
#pragma unroll
    for (int i = 0; i < 4; i += 2) {
        const int b0 = bb + i;
        const int b1 = bb + i + 1;
        const float4* x0 = x + ((size_t)b0 * N_DIM + n) * K_VEC;
        const float4* x1 = x + ((size_t)b1 * N_DIM + n) * K_VEC;

        float4 a0[4], a1[4];
#pragma unroll
        for (int k = 0; k < 4; k++) a0[k] = __ldcs(&x0[lane + 32 * k]);
#pragma unroll
        for (int k = 0; k < 4; k++) a1[k] = __ldcs(&x1[lane + 32 * k]);

        float acc0 = 0.0f, acc1 = 0.0f;
#pragma unroll
        for (int k = 0; k < 4; k++) {
            acc0 = fmaf(a0[k].x, wreg[k].x, acc0);
            acc0 = fmaf(a0[k].y, wreg[k].y, acc0);
            acc0 = fmaf(a0[k].z, wreg[k].z, acc0);
            acc0 = fmaf(a0[k].w, wreg[k].w, acc0);
            acc1 = fmaf(a1[k].x, wreg[k].x, acc1);
            acc1 = fmaf(a1[k].y, wreg[k].y, acc1);
            acc1 = fmaf(a1[k].z, wreg[k].z, acc1);
            acc1 = fmaf(a1[k].w, wreg[k].w, acc1);
        }

#pragma unroll
        for (int off = 16; off > 0; off >>= 1) {
            acc0 += __shfl_xor_sync(0xFFFFFFFFu, acc0, off);
            acc1 += __shfl_xor_sync(0xFFFFFFFFu, acc1, off);
        }

        if (lane == 0) {
            const float s0 = (acc0 >= th) ? 1.0f : 0.0f;
            const float s1 = (acc1 >= th) ? 1.0f : 0.0f;
            spikes[(size_t)b0 * N_DIM + n] = s0;
            spikes[(size_t)b1 * N_DIM + n] = s1;
            cnt += (int)s0 + (int)s1;
        }
    }

    // Per-warp arrival; 32nd arriver finalizes neuron n and resets counters.
    if (lane == 0) {
        atomicAdd(&g_cnt[n], cnt);
        __threadfence();                       // count visible before arrival
        const int arr = atomicAdd(&g_arrivals[n], 1);
        if (arr == 31) {                       // all 32 warps contributed
            __threadfence();                   // acquire all prior counts
            const int total = atomicExch(&g_cnt[n], 0);       // read + reset
            atomicExch(&g_arrivals[n], 0);                    // reset
            const float rate = (float)total * (1.0f / (float)B_DIM);
            const float rh = (1.0f - ALPHA) * r_hat[n] + ALPHA * rate;
            const float thn = theta[n] + THETA_LR * (rh - R_TARGET);
            rates[n]  = rate;
            r_hats[n] = rh;
            thetas[n] = thn;
        }
    }
}

extern "C" void kernel_launch(void* const* d_in, const int* in_sizes, int n_in,
                              void* d_out, int out_size) {
    const float4* x     = (const float4*)d_in[0];   // [B, N, D, S] f32
    const float4* W     = (const float4*)d_in[1];   // [N, D, S] f32
    const float* theta  = (const float*)d_in[2];    // [N]
    const float* r_hat  = (const float*)d_in[3];    // [N]

    float* out    = (float*)d_out;
    float* spikes = out;                       // [B*N]
    float* rates  = out + B_DIM * N_DIM;       // [N]
    float* thetas = rates + N_DIM;             // [N]
    float* r_hats = thetas + N_DIM;            // [N]

    mpjrd_dyn<<<16384, 64>>>(x, W, theta, r_hat,
                             spikes, rates, thetas, r_hats);
}